// round 8
// baseline (speedup 1.0000x reference)
#include <cuda_runtime.h>

#define NB    1024
#define EMB   400
#define RELN  864
#define RNCH  96
#define FSZc  324
#define EPSc  1e-5f

typedef unsigned long long ull;

// ---------------- scratch (static __device__, no allocations) ----------------
__device__ float2 g_sc2[RELN];              // R-BN per-feature {scale, shift}
__device__ float  g_epart[6 * 64 * 2];      // E-stat partials per set
__device__ float  g_ab0[6 * 2];             // BN0 {alpha, beta} per set
__device__ float  g_cpl[6 * RNCH * NB];     // conv-stat lin,  planar [s][c][b]
__device__ float  g_cpq[6 * RNCH * NB];     // conv-stat quad, planar [s][c][b]
__device__ float4 g_ab1[6 * RNCH];          // BN1 affine, duplicated {a,a,c,c}

// ---------------- helpers ----------------
static __device__ __forceinline__ float warpSum(float v) {
#pragma unroll
    for (int o = 16; o > 0; o >>= 1) v += __shfl_xor_sync(0xffffffffu, v, o);
    return v;
}
static __device__ __forceinline__ float warpMax(float v) {
#pragma unroll
    for (int o = 16; o > 0; o >>= 1) v = fmaxf(v, __shfl_xor_sync(0xffffffffu, v, o));
    return v;
}
static __device__ __forceinline__ ull pack2(float lo, float hi) {
    ull r;
    asm("mov.b64 %0, {%1, %2};" : "=l"(r) : "r"(__float_as_uint(lo)), "r"(__float_as_uint(hi)));
    return r;
}
static __device__ __forceinline__ void unpack2(ull v, float& lo, float& hi) {
    unsigned a, b;
    asm("mov.b64 {%0, %1}, %2;" : "=r"(a), "=r"(b) : "l"(v));
    lo = __uint_as_float(a); hi = __uint_as_float(b);
}
static __device__ __forceinline__ ull mul2(ull a, ull b) {
    ull d;
    asm("mul.rn.f32x2 %0, %1, %2;" : "=l"(d) : "l"(a), "l"(b));
    return d;
}
static __device__ __forceinline__ ull add2(ull a, ull b) {
    ull d;
    asm("add.rn.f32x2 %0, %1, %2;" : "=l"(d) : "l"(a), "l"(b));
    return d;
}
static __device__ __forceinline__ ull fma2(ull a, ull b, ull c) {
    ull d;
    asm("fma.rn.f32x2 %0, %1, %2, %3;" : "=l"(d) : "l"(a), "l"(b), "l"(c));
    return d;
}

// ---------------- K1: R-BN per-feature stats -> scale/shift ----------------
__global__ void k_rstats(const int* __restrict__ r_idx, const float* __restrict__ R,
                         const float* __restrict__ g2, const float* __restrict__ b2) {
    int f = blockIdx.x;
    float s = 0.f, ss = 0.f;
    for (int b = threadIdx.x; b < NB; b += blockDim.x) {
        float v = R[(size_t)r_idx[b] * RELN + f];
        s += v; ss += v * v;
    }
    __shared__ float sh[16];
    s = warpSum(s); ss = warpSum(ss);
    int w = threadIdx.x >> 5, l = threadIdx.x & 31;
    if (l == 0) { sh[w] = s; sh[8 + w] = ss; }
    __syncthreads();
    if (threadIdx.x == 0) {
        float S = 0.f, Q = 0.f;
#pragma unroll
        for (int i = 0; i < 8; i++) { S += sh[i]; Q += sh[8 + i]; }
        float mu  = S / (float)NB;
        float var = Q / (float)NB - mu * mu;
        float sc  = g2[f] * rsqrtf(var + EPSc);
        g_sc2[f] = make_float2(sc, b2[f] - mu * sc);
    }
}

// ---------------- K2: E-stat partials per set (no integer division) ----------------
__global__ void k_estats(const int* __restrict__ e1, const int* __restrict__ e2,
                         const int* __restrict__ e3, const int* __restrict__ e4,
                         const int* __restrict__ e5, const int* __restrict__ e6,
                         const float* __restrict__ E) {
    const int* eptr[6] = {e1, e2, e3, e4, e5, e6};
    const int* ei = eptr[blockIdx.y];
    int tid = threadIdx.x;
    float s = 0.f, ss = 0.f;
#pragma unroll 2
    for (int j = 0; j < 16; j++) {
        int b = blockIdx.x * 16 + j;
        const float* row = E + (size_t)ei[b] * EMB;
        for (int d = tid; d < EMB; d += 256) {
            float v = row[d];
            s += v; ss += v * v;
        }
    }
    __shared__ float sh[16];
    s = warpSum(s); ss = warpSum(ss);
    int w = tid >> 5, l = tid & 31;
    if (l == 0) { sh[w] = s; sh[8 + w] = ss; }
    __syncthreads();
    if (tid == 0) {
        float S = 0.f, Q = 0.f;
#pragma unroll
        for (int i = 0; i < 8; i++) { S += sh[i]; Q += sh[8 + i]; }
        int o = (blockIdx.y * 64 + blockIdx.x) * 2;
        g_epart[o] = S; g_epart[o + 1] = Q;
    }
}

// ---------------- K3: finalize BN0 -> alpha/beta per set ----------------
__global__ void k_efin(const float* __restrict__ g0, const float* __restrict__ b0) {
    int s = blockIdx.x, tid = threadIdx.x;
    float su = g_epart[(s * 64 + tid) * 2];
    float sq = g_epart[(s * 64 + tid) * 2 + 1];
    su = warpSum(su); sq = warpSum(sq);
    __shared__ float sh[4];
    if ((tid & 31) == 0) { sh[tid >> 5] = su; sh[2 + (tid >> 5)] = sq; }
    __syncthreads();
    if (tid == 0) {
        float S = sh[0] + sh[1], Q = sh[2] + sh[3];
        float n = (float)NB * (float)EMB;
        float mu = S / n, var = Q / n - mu * mu;
        float alpha = g0[0] * rsqrtf(var + EPSc);
        g_ab0[2 * s]     = alpha;
        g_ab0[2 * s + 1] = b0[0] - mu * alpha;
    }
}

// ---------------- K4: conv stats, warp-partitioned, guard-free unrolled ----------------
// x[b,c,xy] = sum_k patch[k,xy]*r[c,k] -> sum_xy x = r.S ; sum_xy x^2 = r^T C r
// Cst[0..44] = upper-tri C in (i, j>=i) order; Cst[45..53] = S.
// Each warp accumulates its subset of the 54 stats over all 324 positions:
// 10 full 32-lane iterations (xy = 32*it + l, all < 320) + l<4 tail (xy=320+l).
// Position advance is incremental: xy += 32  <=>  X += 1, Y += 14 (wrap at 18).
__global__ void k_cstats(const int* __restrict__ e1, const int* __restrict__ e2,
                         const int* __restrict__ e3, const int* __restrict__ e4,
                         const int* __restrict__ e5, const int* __restrict__ e6,
                         const float* __restrict__ E,
                         const int* __restrict__ r_idx, const float* __restrict__ R) {
    const int* eptr[6] = {e1, e2, e3, e4, e5, e6};
    int b = blockIdx.x, s = blockIdx.y, tid = threadIdx.x;
    __shared__ float en[EMB];
    __shared__ float rns[RELN];
    __shared__ float Cst[54];

    int row = eptr[s][b];
    float al = g_ab0[2 * s], be = g_ab0[2 * s + 1];
    for (int d = tid; d < EMB; d += 128) en[d] = fmaf(E[(size_t)row * EMB + d], al, be);
    size_t rrow = (size_t)r_idx[b] * RELN;
    for (int f = tid; f < RELN; f += 128) {
        float2 sc = g_sc2[f];
        rns[f] = fmaf(R[rrow + f], sc.x, sc.y);
    }
    __syncthreads();

    int w = tid >> 5, l = tid & 31;
    int X0 = (l >= 18) ? 1 : 0;
    int Y0 = l - 18 * X0;
    const float* ep0 = en + X0 * 20 + Y0;

#define LOADP(EP) \
    float p0 = (EP)[0],  p1 = (EP)[1],  p2 = (EP)[2]; \
    float p3 = (EP)[20], p4 = (EP)[21], p5 = (EP)[22]; \
    float p6 = (EP)[40], p7 = (EP)[41], p8 = (EP)[42];
#define A(k,i,j) a[k] = fmaf(p##i, p##j, a[k]);

#define WARP_BODY(NACC, STATS, OFFS) { \
    float a[NACC]; \
    _Pragma("unroll") for (int k = 0; k < NACC; k++) a[k] = 0.f; \
    const float* ep = ep0; int Y = Y0; \
    _Pragma("unroll") \
    for (int it = 0; it < 10; it++) { \
        { LOADP(ep) STATS } \
        ep += 34; Y += 14; \
        if (Y >= 18) { Y -= 18; ep += 2; } \
    } \
    if (l < 4) { LOADP(ep) STATS } \
    _Pragma("unroll") for (int k = 0; k < NACC; k++) { \
        float v = warpSum(a[k]); if (l == 0) Cst[OFFS + k] = v; } \
}

#define STATS_W0 \
    A(0,0,0) A(1,0,1) A(2,0,2) A(3,0,3) A(4,0,4) A(5,0,5) A(6,0,6) \
    A(7,0,7) A(8,0,8) A(9,1,1) A(10,1,2) A(11,1,3) A(12,1,4) A(13,1,5)
#define STATS_W1 \
    A(0,1,6) A(1,1,7) A(2,1,8) A(3,2,2) A(4,2,3) A(5,2,4) A(6,2,5) \
    A(7,2,6) A(8,2,7) A(9,2,8) A(10,3,3) A(11,3,4) A(12,3,5) A(13,3,6)
#define STATS_W2 \
    A(0,3,7) A(1,3,8) A(2,4,4) A(3,4,5) A(4,4,6) A(5,4,7) A(6,4,8) \
    A(7,5,5) A(8,5,6) A(9,5,7) A(10,5,8) A(11,6,6) A(12,6,7) A(13,6,8)
#define STATS_W3 \
    A(0,7,7) A(1,7,8) A(2,8,8) \
    a[3] += p0; a[4] += p1; a[5] += p2; a[6] += p3; a[7] += p4; \
    a[8] += p5; a[9] += p6; a[10] += p7; a[11] += p8;

    if (w == 0)      WARP_BODY(14, STATS_W0, 0)
    else if (w == 1) WARP_BODY(14, STATS_W1, 14)
    else if (w == 2) WARP_BODY(14, STATS_W2, 28)
    else             WARP_BODY(12, STATS_W3, 42)

#undef STATS_W0
#undef STATS_W1
#undef STATS_W2
#undef STATS_W3
#undef WARP_BODY
#undef A
#undef LOADP
    __syncthreads();

    if (tid < RNCH) {
        int c = tid;
        float r9[9];
#pragma unroll
        for (int k = 0; k < 9; k++) r9[k] = rns[c * 9 + k];
        float lin = 0.f;
#pragma unroll
        for (int k = 0; k < 9; k++) lin = fmaf(r9[k], Cst[45 + k], lin);
        // quad = sum_i r_i^2 C_ii + 2 sum_{i<j} r_i r_j C_ij  (triangular order)
        float quad = 0.f;
        int m = 0;
#pragma unroll
        for (int i = 0; i < 9; i++) {
            quad = fmaf(r9[i] * r9[i], Cst[m], quad); m++;
            float t = 0.f;
#pragma unroll
            for (int j = i + 1; j < 9; j++) { t = fmaf(r9[j], Cst[m], t); m++; }
            quad = fmaf(2.f * r9[i], t, quad);
        }
        size_t o = (size_t)(s * RNCH + c) * NB + b;
        g_cpl[o] = lin; g_cpq[o] = quad;
    }
}

// ---------------- K5: finalize BN1 -> per (set,channel) affine (coalesced) ----------------
__global__ void k_ab1(const float* __restrict__ g1, const float* __restrict__ b1) {
    int c = blockIdx.x, s = blockIdx.y, tid = threadIdx.x;
    const float* pl = g_cpl + (size_t)(s * RNCH + c) * NB;
    const float* pq = g_cpq + (size_t)(s * RNCH + c) * NB;
    float sl = 0.f, sq = 0.f;
#pragma unroll
    for (int b = tid; b < NB; b += 256) { sl += pl[b]; sq += pq[b]; }
    __shared__ float sh[16];
    sl = warpSum(sl); sq = warpSum(sq);
    int w = tid >> 5, l = tid & 31;
    if (l == 0) { sh[w] = sl; sh[8 + w] = sq; }
    __syncthreads();
    if (tid == 0) {
        float SL = 0.f, SQ = 0.f;
#pragma unroll
        for (int i = 0; i < 8; i++) { SL += sh[i]; SQ += sh[8 + i]; }
        float n  = (float)NB * (float)FSZc;
        float mu = SL / n, var = SQ / n - mu * mu;
        float a  = g1[c] * rsqrtf(var + EPSc);
        float cc = b1[c] - mu * a;
        g_ab1[s * RNCH + c] = make_float4(a, a, cc, cc);
    }
}

// ---------------- K6: fused conv + BN1 + relu-sum + softmax + product + dot ----------------
// Sets processed in 2 groups of 3: r-taps loaded once per channel feed 3
// independent packed-FMA chains; softmax reductions batched per group.
// Relu-sum via identity sum(relu(v)) = 0.5*(sum(v) + sum(|v|)) — stays packed.
__global__ void __launch_bounds__(192) k_main(
        const int* __restrict__ e1, const int* __restrict__ e2,
        const int* __restrict__ e3, const int* __restrict__ e4,
        const int* __restrict__ e5, const int* __restrict__ e6,
        const float* __restrict__ E, const float* __restrict__ p,
        const int* __restrict__ r_idx, const float* __restrict__ R,
        float* __restrict__ out) {
    const int* eptr[6] = {e1, e2, e3, e4, e5, e6};
    int b = blockIdx.x, tid = threadIdx.x;

    __shared__ __align__(16) float rnd[RNCH * 20];  // duplicated pairs, stride 20 floats
    __shared__ float en[3][EMB];
    __shared__ __align__(16) float4 ab[3][RNCH];
    __shared__ float redM[18];   // per-warp per-set max partials
    __shared__ float redS[18];   // per-warp per-set sum partials
    __shared__ float redR[8];    // [0..2]=M, [4..6]=inv-sum
    __shared__ float redD[8];

    size_t rrow = (size_t)r_idx[b] * RELN;
    for (int f = tid; f < RELN; f += 192) {
        float2 sc = g_sc2[f];
        float v = fmaf(R[rrow + f], sc.x, sc.y);
        int c = f / 9, k = f - c * 9;
        rnd[c * 20 + 2 * k]     = v;
        rnd[c * 20 + 2 * k + 1] = v;
    }

    int rows[6];
#pragma unroll
    for (int s = 0; s < 6; s++) rows[s] = eptr[s][b];

    bool act = tid < 162;
    int x0 = 0, y0 = 0, x1 = 0, y1 = 0;
    if (act) {
        int a0 = 2 * tid, a1 = a0 + 1;
        x0 = a0 / 18; y0 = a0 - 18 * x0;
        x1 = a1 / 18; y1 = a1 - 18 * x1;
    }
    float pl = 1.f, ph = 1.f;
    int w = tid >> 5, l = tid & 31;

#pragma unroll
    for (int g = 0; g < 2; g++) {
        __syncthreads();  // rnd ready (g=0) / previous group's smem reads done (g=1)
#pragma unroll
        for (int ss = 0; ss < 3; ss++) {
            int s = g * 3 + ss;
            float al = g_ab0[2 * s], be = g_ab0[2 * s + 1];
            int row = rows[s];
            for (int d = tid; d < EMB; d += 192)
                en[ss][d] = fmaf(E[(size_t)row * EMB + d], al, be);
        }
        if (tid < RNCH) {
#pragma unroll
            for (int ss = 0; ss < 3; ss++)
                ab[ss][tid] = g_ab1[(g * 3 + ss) * RNCH + tid];
        }
        __syncthreads();

        ull accv[3] = {0ull, 0ull, 0ull};
        ull acca[3] = {0ull, 0ull, 0ull};
        if (act) {
            ull P[3][9];
#pragma unroll
            for (int ss = 0; ss < 3; ss++)
#pragma unroll
                for (int kx = 0; kx < 3; kx++)
#pragma unroll
                    for (int ky = 0; ky < 3; ky++)
                        P[ss][kx * 3 + ky] = pack2(en[ss][(x0 + kx) * 20 + (y0 + ky)],
                                                   en[ss][(x1 + kx) * 20 + (y1 + ky)]);
#pragma unroll 2
            for (int c = 0; c < RNCH; c++) {
                const ulonglong2* rp2 = (const ulonglong2*)(rnd + c * 20);
                ull r[9];
#pragma unroll
                for (int q = 0; q < 4; q++) {
                    ulonglong2 t = rp2[q];
                    r[2 * q] = t.x; r[2 * q + 1] = t.y;
                }
                r[8] = ((const ull*)(rnd + c * 20))[8];
#pragma unroll
                for (int ss = 0; ss < 3; ss++) {
                    ull a = mul2(P[ss][0], r[0]);
#pragma unroll
                    for (int k = 1; k < 9; k++) a = fma2(P[ss][k], r[k], a);
                    const ull* abp = (const ull*)(&ab[ss][c]);
                    ull v2 = fma2(abp[0], a, abp[1]);   // a*x + c (packed)
                    accv[ss] = add2(accv[ss], v2);
                    acca[ss] = add2(acca[ss], v2 & 0x7fffffff7fffffffULL);
                }
            }
        }

        // ---- batched softmax for 3 sets ----
        float ylo[3], yhi[3];
#pragma unroll
        for (int ss = 0; ss < 3; ss++) {
            float vl, vh, ql, qh;
            unpack2(accv[ss], vl, vh);
            unpack2(acca[ss], ql, qh);
            ylo[ss] = 0.5f * (vl + ql);
            yhi[ss] = 0.5f * (vh + qh);
            float m = act ? fmaxf(ylo[ss], yhi[ss]) : -3.0e38f;
            m = warpMax(m);
            if (l == 0) redM[ss * 6 + w] = m;
        }
        __syncthreads();
        if (tid < 3) {
            float v = redM[tid * 6];
#pragma unroll
            for (int i = 1; i < 6; i++) v = fmaxf(v, redM[tid * 6 + i]);
            redR[tid] = v;
        }
        __syncthreads();
        float el[3], eh[3];
#pragma unroll
        for (int ss = 0; ss < 3; ss++) {
            float M = redR[ss];
            el[ss] = act ? __expf(ylo[ss] - M) : 0.f;
            eh[ss] = act ? __expf(yhi[ss] - M) : 0.f;
            float sm = warpSum(el[ss] + eh[ss]);
            if (l == 0) redS[ss * 6 + w] = sm;
        }
        __syncthreads();
        if (tid < 3) {
            float v = 0.f;
#pragma unroll
            for (int i = 0; i < 6; i++) v += redS[tid * 6 + i];
            redR[4 + tid] = __frcp_rn(v);
        }
        __syncthreads();
#pragma unroll
        for (int ss = 0; ss < 3; ss++) {
            float inv = redR[4 + ss];
            bool pad = (rows[g * 3 + ss] == 0);  // padding entity -> uniform 1/324
            pl *= pad ? (1.0f / (float)FSZc) : el[ss] * inv;
            ph *= pad ? (1.0f / (float)FSZc) : eh[ss] * inv;
        }
    }

    float d = act ? fmaf(pl, p[2 * tid], ph * p[2 * tid + 1]) : 0.f;
    d = warpSum(d);
    if (l == 0) redD[w] = d;
    __syncthreads();
    if (tid == 0) {
        float v = 0.f;
#pragma unroll
        for (int i = 0; i < 6; i++) v += redD[i];
        out[b] = v;
    }
}

// ---------------- launch ----------------
extern "C" void kernel_launch(void* const* d_in, const int* in_sizes, int n_in,
                              void* d_out, int out_size) {
    (void)in_sizes; (void)n_in; (void)out_size;
    const int*   r_idx = (const int*)d_in[0];
    const int*   e1 = (const int*)d_in[1];
    const int*   e2 = (const int*)d_in[2];
    const int*   e3 = (const int*)d_in[3];
    const int*   e4 = (const int*)d_in[4];
    const int*   e5 = (const int*)d_in[5];
    const int*   e6 = (const int*)d_in[6];
    const float* E  = (const float*)d_in[7];
    const float* R  = (const float*)d_in[8];
    const float* g0 = (const float*)d_in[9];
    const float* b0 = (const float*)d_in[10];
    const float* g1 = (const float*)d_in[11];
    const float* b1 = (const float*)d_in[12];
    const float* g2 = (const float*)d_in[13];
    const float* b2 = (const float*)d_in[14];
    const float* p  = (const float*)d_in[15];
    float* out = (float*)d_out;

    k_rstats<<<RELN, 256>>>(r_idx, R, g2, b2);
    k_estats<<<dim3(64, 6), 256>>>(e1, e2, e3, e4, e5, e6, E);
    k_efin<<<6, 64>>>(g0, b0);
    k_cstats<<<dim3(NB, 6), 128>>>(e1, e2, e3, e4, e5, e6, E, r_idx, R);
    k_ab1<<<dim3(RNCH, 6), 256>>>(g1, b1);
    k_main<<<NB, 192>>>(e1, e2, e3, e4, e5, e6, E, p, r_idx, R, out);
}

// round 12
// speedup vs baseline: 1.0934x; 1.0934x over previous
#include <cuda_runtime.h>

#define NB    1024
#define EMB   400
#define RELN  864
#define RNCH  96
#define FSZc  324
#define EPSc  1e-5f

typedef unsigned long long ull;

// ---------------- scratch (static __device__, no allocations) ----------------
__device__ float2 g_sc2[RELN];              // R-BN per-feature {scale, shift}
__device__ float  g_epart[6 * 64 * 2];      // E-stat partials per set
__device__ float  g_ab0[6 * 2];             // BN0 {alpha, beta} per set
__device__ float  g_cpl[6 * RNCH * NB];     // conv-stat lin,  planar [s][c][b]
__device__ float  g_cpq[6 * RNCH * NB];     // conv-stat quad, planar [s][c][b]
__device__ float4 g_ab1[6 * RNCH];          // BN1 affine, duplicated {a,a,c,c}

// ---------------- helpers ----------------
static __device__ __forceinline__ float warpSum(float v) {
#pragma unroll
    for (int o = 16; o > 0; o >>= 1) v += __shfl_xor_sync(0xffffffffu, v, o);
    return v;
}
static __device__ __forceinline__ float warpMax(float v) {
#pragma unroll
    for (int o = 16; o > 0; o >>= 1) v = fmaxf(v, __shfl_xor_sync(0xffffffffu, v, o));
    return v;
}
static __device__ __forceinline__ ull pack2(float lo, float hi) {
    ull r;
    asm("mov.b64 %0, {%1, %2};" : "=l"(r) : "r"(__float_as_uint(lo)), "r"(__float_as_uint(hi)));
    return r;
}
static __device__ __forceinline__ void unpack2(ull v, float& lo, float& hi) {
    unsigned a, b;
    asm("mov.b64 {%0, %1}, %2;" : "=r"(a), "=r"(b) : "l"(v));
    lo = __uint_as_float(a); hi = __uint_as_float(b);
}
static __device__ __forceinline__ ull mul2(ull a, ull b) {
    ull d;
    asm("mul.rn.f32x2 %0, %1, %2;" : "=l"(d) : "l"(a), "l"(b));
    return d;
}
static __device__ __forceinline__ ull add2(ull a, ull b) {
    ull d;
    asm("add.rn.f32x2 %0, %1, %2;" : "=l"(d) : "l"(a), "l"(b));
    return d;
}
static __device__ __forceinline__ ull fma2(ull a, ull b, ull c) {
    ull d;
    asm("fma.rn.f32x2 %0, %1, %2, %3;" : "=l"(d) : "l"(a), "l"(b), "l"(c));
    return d;
}

// ---------------- K1: R-BN per-feature stats -> scale/shift ----------------
__global__ void k_rstats(const int* __restrict__ r_idx, const float* __restrict__ R,
                         const float* __restrict__ g2, const float* __restrict__ b2) {
    int f = blockIdx.x;
    float s = 0.f, ss = 0.f;
    for (int b = threadIdx.x; b < NB; b += blockDim.x) {
        float v = R[(size_t)r_idx[b] * RELN + f];
        s += v; ss += v * v;
    }
    __shared__ float sh[16];
    s = warpSum(s); ss = warpSum(ss);
    int w = threadIdx.x >> 5, l = threadIdx.x & 31;
    if (l == 0) { sh[w] = s; sh[8 + w] = ss; }
    __syncthreads();
    if (threadIdx.x == 0) {
        float S = 0.f, Q = 0.f;
#pragma unroll
        for (int i = 0; i < 8; i++) { S += sh[i]; Q += sh[8 + i]; }
        float mu  = S / (float)NB;
        float var = Q / (float)NB - mu * mu;
        float sc  = g2[f] * rsqrtf(var + EPSc);
        g_sc2[f] = make_float2(sc, b2[f] - mu * sc);
    }
}

// ---------------- K2: E-stat partials per set (no integer division) ----------------
__global__ void k_estats(const int* __restrict__ e1, const int* __restrict__ e2,
                         const int* __restrict__ e3, const int* __restrict__ e4,
                         const int* __restrict__ e5, const int* __restrict__ e6,
                         const float* __restrict__ E) {
    const int* eptr[6] = {e1, e2, e3, e4, e5, e6};
    const int* ei = eptr[blockIdx.y];
    int tid = threadIdx.x;
    float s = 0.f, ss = 0.f;
#pragma unroll 2
    for (int j = 0; j < 16; j++) {
        int b = blockIdx.x * 16 + j;
        const float* row = E + (size_t)ei[b] * EMB;
        for (int d = tid; d < EMB; d += 256) {
            float v = row[d];
            s += v; ss += v * v;
        }
    }
    __shared__ float sh[16];
    s = warpSum(s); ss = warpSum(ss);
    int w = tid >> 5, l = tid & 31;
    if (l == 0) { sh[w] = s; sh[8 + w] = ss; }
    __syncthreads();
    if (tid == 0) {
        float S = 0.f, Q = 0.f;
#pragma unroll
        for (int i = 0; i < 8; i++) { S += sh[i]; Q += sh[8 + i]; }
        int o = (blockIdx.y * 64 + blockIdx.x) * 2;
        g_epart[o] = S; g_epart[o + 1] = Q;
    }
}

// ---------------- K3: finalize BN0 -> alpha/beta per set ----------------
__global__ void k_efin(const float* __restrict__ g0, const float* __restrict__ b0) {
    int s = blockIdx.x, tid = threadIdx.x;
    float su = g_epart[(s * 64 + tid) * 2];
    float sq = g_epart[(s * 64 + tid) * 2 + 1];
    su = warpSum(su); sq = warpSum(sq);
    __shared__ float sh[4];
    if ((tid & 31) == 0) { sh[tid >> 5] = su; sh[2 + (tid >> 5)] = sq; }
    __syncthreads();
    if (tid == 0) {
        float S = sh[0] + sh[1], Q = sh[2] + sh[3];
        float n = (float)NB * (float)EMB;
        float mu = S / n, var = Q / n - mu * mu;
        float alpha = g0[0] * rsqrtf(var + EPSc);
        g_ab0[2 * s]     = alpha;
        g_ab0[2 * s + 1] = b0[0] - mu * alpha;
    }
}

// ---------------- K4: conv stats, ONE CTA per sample, one warp per set ----------------
// x[b,c,xy] = sum_k patch[k,xy]*r[c,k] -> sum_xy x = r.S ; sum_xy x^2 = r^T C r
// Warp w computes ALL 54 stats for set s=w in registers (9 LDS feed 54 FMA per
// round -> fma-bound, not LDS-bound). rns loaded/normalized once per sample.
// Cst layout: [0..44] upper-tri C in (i, j>=i) order; [45..53] = S.
__global__ void __launch_bounds__(192) k_cstats(
        const int* __restrict__ e1, const int* __restrict__ e2,
        const int* __restrict__ e3, const int* __restrict__ e4,
        const int* __restrict__ e5, const int* __restrict__ e6,
        const float* __restrict__ E,
        const int* __restrict__ r_idx, const float* __restrict__ R) {
    const int* eptr[6] = {e1, e2, e3, e4, e5, e6};
    int b = blockIdx.x, tid = threadIdx.x;
    __shared__ float en[6][EMB];
    __shared__ float rns[RELN];
    __shared__ float Cst[6][54];

#pragma unroll
    for (int s = 0; s < 6; s++) {
        int row = eptr[s][b];
        float al = g_ab0[2 * s], be = g_ab0[2 * s + 1];
        for (int d = tid; d < EMB; d += 192)
            en[s][d] = fmaf(E[(size_t)row * EMB + d], al, be);
    }
    size_t rrow = (size_t)r_idx[b] * RELN;
    for (int f = tid; f < RELN; f += 192) {
        float2 sc = g_sc2[f];
        rns[f] = fmaf(R[rrow + f], sc.x, sc.y);
    }
    __syncthreads();

    int w = tid >> 5, l = tid & 31;
    {
        const float* enw = en[w];
        float a[54];
#pragma unroll
        for (int k = 0; k < 54; k++) a[k] = 0.f;
        int X0 = (l >= 18) ? 1 : 0;
        int Y0 = l - 18 * X0;
        const float* ep = enw + X0 * 20 + Y0;
        int Y = Y0;

#define LOADP(EP) \
    float p0 = (EP)[0],  p1 = (EP)[1],  p2 = (EP)[2]; \
    float p3 = (EP)[20], p4 = (EP)[21], p5 = (EP)[22]; \
    float p6 = (EP)[40], p7 = (EP)[41], p8 = (EP)[42];
#define A(k,i,j) a[k] = fmaf(p##i, p##j, a[k]);
#define ALLSTATS \
    A(0,0,0) A(1,0,1) A(2,0,2) A(3,0,3) A(4,0,4) A(5,0,5) A(6,0,6) A(7,0,7) A(8,0,8) \
    A(9,1,1) A(10,1,2) A(11,1,3) A(12,1,4) A(13,1,5) A(14,1,6) A(15,1,7) A(16,1,8) \
    A(17,2,2) A(18,2,3) A(19,2,4) A(20,2,5) A(21,2,6) A(22,2,7) A(23,2,8) \
    A(24,3,3) A(25,3,4) A(26,3,5) A(27,3,6) A(28,3,7) A(29,3,8) \
    A(30,4,4) A(31,4,5) A(32,4,6) A(33,4,7) A(34,4,8) \
    A(35,5,5) A(36,5,6) A(37,5,7) A(38,5,8) \
    A(39,6,6) A(40,6,7) A(41,6,8) \
    A(42,7,7) A(43,7,8) A(44,8,8) \
    a[45] += p0; a[46] += p1; a[47] += p2; a[48] += p3; a[49] += p4; \
    a[50] += p5; a[51] += p6; a[52] += p7; a[53] += p8;

        // xy = 32*it + l; advance xy += 32 <=> X += 1, Y += 14 (wrap at 18):
        // ep += 20+14 = 34, +2 more when Y wraps. 10 full rounds cover xy<320;
        // tail l<4 covers 320..323.
#pragma unroll
        for (int it = 0; it < 10; it++) {
            { LOADP(ep) ALLSTATS }
            ep += 34; Y += 14;
            if (Y >= 18) { Y -= 18; ep += 2; }
        }
        if (l < 4) { LOADP(ep) ALLSTATS }
#undef ALLSTATS
#undef A
#undef LOADP

#pragma unroll
        for (int k = 0; k < 54; k++) {
            float v = warpSum(a[k]);
            if (l == 0) Cst[w][k] = v;
        }
    }
    __syncthreads();

    // lin/quad epilogue: thread t -> channel t%96, sets 3*(t/96)+{0,1,2}
    int c = tid % RNCH, half = tid / RNCH;
    float r9[9];
#pragma unroll
    for (int k = 0; k < 9; k++) r9[k] = rns[c * 9 + k];
#pragma unroll
    for (int ss = 0; ss < 3; ss++) {
        int s = half * 3 + ss;
        const float* Cs = Cst[s];
        float lin = 0.f;
#pragma unroll
        for (int k = 0; k < 9; k++) lin = fmaf(r9[k], Cs[45 + k], lin);
        float quad = 0.f;
        int m = 0;
#pragma unroll
        for (int i = 0; i < 9; i++) {
            quad = fmaf(r9[i] * r9[i], Cs[m], quad); m++;
            float t = 0.f;
#pragma unroll
            for (int j = i + 1; j < 9; j++) { t = fmaf(r9[j], Cs[m], t); m++; }
            quad = fmaf(2.f * r9[i], t, quad);
        }
        size_t o = (size_t)(s * RNCH + c) * NB + b;
        g_cpl[o] = lin; g_cpq[o] = quad;
    }
}

// ---------------- K5: finalize BN1 -> per (set,channel) affine (coalesced) ----------------
__global__ void k_ab1(const float* __restrict__ g1, const float* __restrict__ b1) {
    int c = blockIdx.x, s = blockIdx.y, tid = threadIdx.x;
    const float* pl = g_cpl + (size_t)(s * RNCH + c) * NB;
    const float* pq = g_cpq + (size_t)(s * RNCH + c) * NB;
    float sl = 0.f, sq = 0.f;
#pragma unroll
    for (int b = tid; b < NB; b += 256) { sl += pl[b]; sq += pq[b]; }
    __shared__ float sh[16];
    sl = warpSum(sl); sq = warpSum(sq);
    int w = tid >> 5, l = tid & 31;
    if (l == 0) { sh[w] = sl; sh[8 + w] = sq; }
    __syncthreads();
    if (tid == 0) {
        float SL = 0.f, SQ = 0.f;
#pragma unroll
        for (int i = 0; i < 8; i++) { SL += sh[i]; SQ += sh[8 + i]; }
        float n  = (float)NB * (float)FSZc;
        float mu = SL / n, var = SQ / n - mu * mu;
        float a  = g1[c] * rsqrtf(var + EPSc);
        float cc = b1[c] - mu * a;
        g_ab1[s * RNCH + c] = make_float4(a, a, cc, cc);
    }
}

// ---------------- K6: fused conv + BN1 + relu-sum + softmax + product + dot ----------------
// (R6 body — packed-FMA over 2 groups of 3 sets; relu via unpack+fmax.)
__global__ void __launch_bounds__(192) k_main(
        const int* __restrict__ e1, const int* __restrict__ e2,
        const int* __restrict__ e3, const int* __restrict__ e4,
        const int* __restrict__ e5, const int* __restrict__ e6,
        const float* __restrict__ E, const float* __restrict__ p,
        const int* __restrict__ r_idx, const float* __restrict__ R,
        float* __restrict__ out) {
    const int* eptr[6] = {e1, e2, e3, e4, e5, e6};
    int b = blockIdx.x, tid = threadIdx.x;

    __shared__ __align__(16) float rnd[RNCH * 20];  // duplicated pairs, stride 20 floats
    __shared__ float en[3][EMB];
    __shared__ __align__(16) float4 ab[3][RNCH];
    __shared__ float redM[18];   // per-warp per-set max partials
    __shared__ float redS[18];   // per-warp per-set sum partials
    __shared__ float redR[8];    // [0..2]=M, [4..6]=inv-sum
    __shared__ float redD[8];

    size_t rrow = (size_t)r_idx[b] * RELN;
    for (int f = tid; f < RELN; f += 192) {
        float2 sc = g_sc2[f];
        float v = fmaf(R[rrow + f], sc.x, sc.y);
        int c = f / 9, k = f - c * 9;
        rnd[c * 20 + 2 * k]     = v;
        rnd[c * 20 + 2 * k + 1] = v;
    }

    int rows[6];
#pragma unroll
    for (int s = 0; s < 6; s++) rows[s] = eptr[s][b];

    bool act = tid < 162;
    int x0 = 0, y0 = 0, x1 = 0, y1 = 0;
    if (act) {
        int a0 = 2 * tid, a1 = a0 + 1;
        x0 = a0 / 18; y0 = a0 - 18 * x0;
        x1 = a1 / 18; y1 = a1 - 18 * x1;
    }
    float pl = 1.f, ph = 1.f;
    int w = tid >> 5, l = tid & 31;

#pragma unroll
    for (int g = 0; g < 2; g++) {
        __syncthreads();  // rnd ready (g=0) / previous group's smem reads done (g=1)
#pragma unroll
        for (int ss = 0; ss < 3; ss++) {
            int s = g * 3 + ss;
            float al = g_ab0[2 * s], be = g_ab0[2 * s + 1];
            int row = rows[s];
            for (int d = tid; d < EMB; d += 192)
                en[ss][d] = fmaf(E[(size_t)row * EMB + d], al, be);
        }
        if (tid < RNCH) {
#pragma unroll
            for (int ss = 0; ss < 3; ss++)
                ab[ss][tid] = g_ab1[(g * 3 + ss) * RNCH + tid];
        }
        __syncthreads();

        ull acc2[3] = {0ull, 0ull, 0ull};
        if (act) {
            ull P[3][9];
#pragma unroll
            for (int ss = 0; ss < 3; ss++)
#pragma unroll
                for (int kx = 0; kx < 3; kx++)
#pragma unroll
                    for (int ky = 0; ky < 3; ky++)
                        P[ss][kx * 3 + ky] = pack2(en[ss][(x0 + kx) * 20 + (y0 + ky)],
                                                   en[ss][(x1 + kx) * 20 + (y1 + ky)]);
#pragma unroll 2
            for (int c = 0; c < RNCH; c++) {
                const ulonglong2* rp2 = (const ulonglong2*)(rnd + c * 20);
                ull r[9];
#pragma unroll
                for (int q = 0; q < 4; q++) {
                    ulonglong2 t = rp2[q];
                    r[2 * q] = t.x; r[2 * q + 1] = t.y;
                }
                r[8] = ((const ull*)(rnd + c * 20))[8];
#pragma unroll
                for (int ss = 0; ss < 3; ss++) {
                    ull a = mul2(P[ss][0], r[0]);
#pragma unroll
                    for (int k = 1; k < 9; k++) a = fma2(P[ss][k], r[k], a);
                    const ull* abp = (const ull*)(&ab[ss][c]);
                    ull v2 = fma2(abp[0], a, abp[1]);   // a*x + c (packed)
                    float lo, hi; unpack2(v2, lo, hi);
                    acc2[ss] = add2(acc2[ss], pack2(fmaxf(lo, 0.f), fmaxf(hi, 0.f)));
                }
            }
        }

        // ---- batched softmax for 3 sets ----
        float ylo[3], yhi[3];
#pragma unroll
        for (int ss = 0; ss < 3; ss++) {
            unpack2(acc2[ss], ylo[ss], yhi[ss]);
            float m = act ? fmaxf(ylo[ss], yhi[ss]) : -3.0e38f;
            m = warpMax(m);
            if (l == 0) redM[ss * 6 + w] = m;
        }
        __syncthreads();
        if (tid < 3) {
            float v = redM[tid * 6];
#pragma unroll
            for (int i = 1; i < 6; i++) v = fmaxf(v, redM[tid * 6 + i]);
            redR[tid] = v;
        }
        __syncthreads();
        float el[3], eh[3];
#pragma unroll
        for (int ss = 0; ss < 3; ss++) {
            float M = redR[ss];
            el[ss] = act ? __expf(ylo[ss] - M) : 0.f;
            eh[ss] = act ? __expf(yhi[ss] - M) : 0.f;
            float sm = warpSum(el[ss] + eh[ss]);
            if (l == 0) redS[ss * 6 + w] = sm;
        }
        __syncthreads();
        if (tid < 3) {
            float v = 0.f;
#pragma unroll
            for (int i = 0; i < 6; i++) v += redS[tid * 6 + i];
            redR[4 + tid] = __frcp_rn(v);
        }
        __syncthreads();
#pragma unroll
        for (int ss = 0; ss < 3; ss++) {
            float inv = redR[4 + ss];
            bool pad = (rows[g * 3 + ss] == 0);  // padding entity -> uniform 1/324
            pl *= pad ? (1.0f / (float)FSZc) : el[ss] * inv;
            ph *= pad ? (1.0f / (float)FSZc) : eh[ss] * inv;
        }
    }

    float d = act ? fmaf(pl, p[2 * tid], ph * p[2 * tid + 1]) : 0.f;
    d = warpSum(d);
    if (l == 0) redD[w] = d;
    __syncthreads();
    if (tid == 0) {
        float v = 0.f;
#pragma unroll
        for (int i = 0; i < 6; i++) v += redD[i];
        out[b] = v;
    }
}

// ---------------- launch ----------------
extern "C" void kernel_launch(void* const* d_in, const int* in_sizes, int n_in,
                              void* d_out, int out_size) {
    (void)in_sizes; (void)n_in; (void)out_size;
    const int*   r_idx = (const int*)d_in[0];
    const int*   e1 = (const int*)d_in[1];
    const int*   e2 = (const int*)d_in[2];
    const int*   e3 = (const int*)d_in[3];
    const int*   e4 = (const int*)d_in[4];
    const int*   e5 = (const int*)d_in[5];
    const int*   e6 = (const int*)d_in[6];
    const float* E  = (const float*)d_in[7];
    const float* R  = (const float*)d_in[8];
    const float* g0 = (const float*)d_in[9];
    const float* b0 = (const float*)d_in[10];
    const float* g1 = (const float*)d_in[11];
    const float* b1 = (const float*)d_in[12];
    const float* g2 = (const float*)d_in[13];
    const float* b2 = (const float*)d_in[14];
    const float* p  = (const float*)d_in[15];
    float* out = (float*)d_out;

    k_rstats<<<RELN, 256>>>(r_idx, R, g2, b2);
    k_estats<<<dim3(64, 6), 256>>>(e1, e2, e3, e4, e5, e6, E);
    k_efin<<<6, 64>>>(g0, b0);
    k_cstats<<<NB, 192>>>(e1, e2, e3, e4, e5, e6, E, r_idx, R);
    k_ab1<<<dim3(RNCH, 6), 256>>>(g1, b1);
    k_main<<<NB, 192>>>(e1, e2, e3, e4, e5, e6, E, p, r_idx, R, out);
}